// round 1
// baseline (speedup 1.0000x reference)
#include <cuda_runtime.h>

// Fold: x (B=8, C=32, K1=8, K2=8, L=4096) -> out (B, C, H=260, W=260)
// kernel (8,8), stride (4,4), n = sqrt(L) = 64.
// Gather formulation: out[b,c,oh,ow] = sum over di in {oh&3, oh&3+4},
// dj in {ow&3, ow&3+4} (where the patch index is in range) of
// x[b, c, di, dj, i*n + j] with i=(oh-di)/4, j=(ow-dj)/4.

namespace {
constexpr int B = 8;
constexpr int C = 32;
constexpr int K = 8;
constexpr int S = 4;
constexpr int N = 64;      // patch grid n x n
constexpr int L = N * N;   // 4096
constexpr int H = S * (N - 1) + K;  // 260
constexpr int W = S * (N - 1) + K;  // 260
constexpr long long TOTAL = (long long)B * C * H * W;  // 17,305,600
}

__global__ __launch_bounds__(256) void fold_gather_kernel(
    const float* __restrict__ x, float* __restrict__ out) {
    long long idx = (long long)blockIdx.x * blockDim.x + threadIdx.x;
    if (idx >= TOTAL) return;

    int ow = (int)(idx % W);
    long long t = idx / W;
    int oh = (int)(t % H);
    long long bc = t / H;          // 0 .. B*C-1

    const float* __restrict__ xb = x + bc * (long long)(K * K * L);

    int di0 = oh & 3;
    int di1 = di0 + 4;
    int dj0 = ow & 3;
    int dj1 = dj0 + 4;

    int i0 = (oh - di0) >> 2;
    int i1 = (oh - di1) >> 2;
    int j0 = (ow - dj0) >> 2;
    int j1 = (ow - dj1) >> 2;

    bool vi0 = (unsigned)i0 < (unsigned)N;   // i0 >= 0 always; check < N
    bool vi1 = (unsigned)i1 < (unsigned)N;   // i1 may be -1 near top edge
    bool vj0 = (unsigned)j0 < (unsigned)N;
    bool vj1 = (unsigned)j1 < (unsigned)N;

    // Base offsets per (di,dj) plane; patch offset i*N + j.
    float a00 = 0.f, a01 = 0.f, a10 = 0.f, a11 = 0.f;
    if (vi0 && vj0) a00 = xb[(di0 * K + dj0) * L + i0 * N + j0];
    if (vi0 && vj1) a01 = xb[(di0 * K + dj1) * L + i0 * N + j1];
    if (vi1 && vj0) a10 = xb[(di1 * K + dj0) * L + i1 * N + j0];
    if (vi1 && vj1) a11 = xb[(di1 * K + dj1) * L + i1 * N + j1];

    out[idx] = (a00 + a01) + (a10 + a11);
}

extern "C" void kernel_launch(void* const* d_in, const int* in_sizes, int n_in,
                              void* d_out, int out_size) {
    const float* x = (const float*)d_in[0];
    float* out = (float*)d_out;
    int threads = 256;
    long long blocks = (TOTAL + threads - 1) / threads;  // 67,600
    fold_gather_kernel<<<(unsigned)blocks, threads>>>(x, out);
}

// round 2
// speedup vs baseline: 1.3519x; 1.3519x over previous
#include <cuda_runtime.h>

// Fold: x (B=8, C=32, K1=8, K2=8, L=4096) -> out (B, C, H=260, W=260)
// kernel (8,8), stride (4,4), n = 64.
// Quad-gather: each thread computes 4 consecutive ow = 4q+{0,1,2,3}.
// For ow=4q+r: dj0=r (j=q), dj1=r+4 (j=q-1). All 16 input loads for the quad
// sit at column q or q-1 of 16 planes; warps with consecutive q therefore make
// fully-coalesced 128B line loads. Output written as float4.

namespace {
constexpr int B = 8;
constexpr int C = 32;
constexpr int K = 8;
constexpr int N = 64;               // patch grid
constexpr int L = N * N;            // 4096
constexpr int H = 260;
constexpr int W = 260;
constexpr int QW = W / 4;           // 65 quads per row
constexpr int TOTAL_Q = B * C * H * QW;  // 4,326,400
}

__global__ __launch_bounds__(256) void fold_quad_kernel(
    const float* __restrict__ x, float* __restrict__ out) {
    int tid = blockIdx.x * blockDim.x + threadIdx.x;
    if (tid >= TOTAL_Q) return;

    int q  = tid % QW;          // 0..64
    int t  = tid / QW;
    int oh = t % H;             // 0..259
    int bc = t / H;             // 0..255

    const float* __restrict__ xb = x + (long long)bc * (K * K * L);

    int di0 = oh & 3;
    int di1 = di0 + 4;
    int i0  = oh >> 2;          // row for di0
    int i1  = i0 - 1;           // row for di1

    bool vi0 = i0 < N;          // i0 can be 64 when oh>=256
    bool vi1 = i1 >= 0;         // i1 can be -1 when oh<4
    bool vj0 = q < N;           // q can be 64 on last quad
    bool vj1 = q >= 1;

    // Plane row bases (offset of element j=0 of row i in plane (di,dj)).
    // plane(di,dj) starts at (di*K+dj)*L.
    int row0 = i0 * N;          // within-plane row offset for di0
    int row1 = i1 * N;          // for di1

    float a[4], b[4], c[4], d[4];
    bool v00 = vi0 && vj0, v01 = vi0 && vj1;
    bool v10 = vi1 && vj0, v11 = vi1 && vj1;

#pragma unroll
    for (int r = 0; r < 4; r++) {
        // plane (di0, r), column q
        a[r] = v00 ? xb[(di0 * K + r) * L + row0 + q] : 0.f;
        // plane (di0, r+4), column q-1
        b[r] = v01 ? xb[(di0 * K + r + 4) * L + row0 + q - 1] : 0.f;
        // plane (di1, r), column q
        c[r] = v10 ? xb[(di1 * K + r) * L + row1 + q] : 0.f;
        // plane (di1, r+4), column q-1
        d[r] = v11 ? xb[(di1 * K + r + 4) * L + row1 + q - 1] : 0.f;
    }

    float4 o;
    o.x = (a[0] + b[0]) + (c[0] + d[0]);
    o.y = (a[1] + b[1]) + (c[1] + d[1]);
    o.z = (a[2] + b[2]) + (c[2] + d[2]);
    o.w = (a[3] + b[3]) + (c[3] + d[3]);

    // out index: bc*H*W + oh*W + 4q  — 16B aligned (260 = 4*65).
    float4* outv = (float4*)(out + (long long)bc * (H * W) + oh * W);
    outv[q] = o;
}

extern "C" void kernel_launch(void* const* d_in, const int* in_sizes, int n_in,
                              void* d_out, int out_size) {
    const float* x = (const float*)d_in[0];
    float* out = (float*)d_out;
    int threads = 256;
    int blocks = (TOTAL_Q + threads - 1) / threads;  // 16,900
    fold_quad_kernel<<<blocks, threads>>>(x, out);
}